// round 10
// baseline (speedup 1.0000x reference)
#include <cuda_runtime.h>
#include <cuda_bf16.h>
#include <math.h>

#define NN 20000
#define NE 320000
#define NE2 (NE + NN)
#define H 128
#define HEADS 4
#define HH 512   // HEADS*H

// weight/x split-pool offsets (elements)
#define OFF_X    0
#define OFF_EMB  320000                 // NN*16
#define OFF_LINL (OFF_EMB + 2048)       // 322048
#define OFF_LINR (OFF_LINL + 196608)    // 518656
#define OFF_PROJ (OFF_LINR + 196608)    // 715264
#define OFF_FW1  (OFF_PROJ + 131072)    // 846336
#define OFF_FW2  (OFF_FW1 + 98304)      // 944640
#define W_TOTAL  (OFF_FW2 + 98304)      // 1042944

// ---------------- static scratch (no allocation allowed) ----------------
__device__ float g_h[NN * H];
__device__ float g_t[NN * H];
__device__ float g_xl[NN * HH];
__device__ float g_xr[NN * HH];
__device__ float g_agg[NN * HH];
__device__ float g_la[NN * 2];
__device__ int   g_deg[NN];
__device__ int   g_rowptr[NN + 1];
__device__ int   g_cursor[NN];
__device__ int   g_csr[NE2];
__device__ int   g_bsum[32];

__device__ __align__(16) __nv_bfloat16 g_w_hi[W_TOTAL];
__device__ __align__(16) __nv_bfloat16 g_w_lo[W_TOTAL];
__device__ __align__(16) __nv_bfloat16 g_hs_hi[NN * H];
__device__ __align__(16) __nv_bfloat16 g_hs_lo[NN * H];
__device__ __align__(16) __nv_bfloat16 g_aggs_hi[NN * HH];
__device__ __align__(16) __nv_bfloat16 g_aggs_lo[NN * HH];
__device__ __align__(16) __nv_bfloat16 g_ffns_hi[NN * 256];
__device__ __align__(16) __nv_bfloat16 g_ffns_lo[NN * 256];

// ---------------- graph setup ----------------
__global__ void zero_kernel() {
    int i = blockIdx.x * blockDim.x + threadIdx.x;
    if (i < NN) {
        g_deg[i] = 0;
        g_cursor[i] = 0;
        g_la[2 * i] = 0.f;
        g_la[2 * i + 1] = 0.f;
    }
}

__global__ void deg_kernel(const int* __restrict__ ei, const float* __restrict__ ea) {
    int e = blockIdx.x * blockDim.x + threadIdx.x;
    if (e < NE) {
        int dst = ei[NE + e];
        atomicAdd(&g_deg[dst], 1);
        atomicAdd(&g_la[2 * dst],     ea[2 * e]);
        atomicAdd(&g_la[2 * dst + 1], ea[2 * e + 1]);
    }
}

__global__ void loopattr_kernel() {
    int n = blockIdx.x * blockDim.x + threadIdx.x;
    if (n < NN) {
        float d = fmaxf((float)g_deg[n], 1.0f);
        g_la[2 * n]     /= d;
        g_la[2 * n + 1] /= d;
    }
}

__global__ void scan1_kernel() {
    __shared__ int ws[32];
    int b = blockIdx.x, t = threadIdx.x;
    int i = b * 1024 + t;
    int lane = t & 31, w = t >> 5;
    int x = (i < NN) ? (g_deg[i] + 1) : 0;
#pragma unroll
    for (int o = 1; o < 32; o <<= 1) {
        int y = __shfl_up_sync(0xffffffffu, x, o);
        if (lane >= o) x += y;
    }
    if (lane == 31) ws[w] = x;
    __syncthreads();
    if (w == 0) {
        int s = ws[lane];
#pragma unroll
        for (int o = 1; o < 32; o <<= 1) {
            int y = __shfl_up_sync(0xffffffffu, s, o);
            if (lane >= o) s += y;
        }
        ws[lane] = s;
    }
    __syncthreads();
    int off = (w > 0) ? ws[w - 1] : 0;
    x += off;
    if (i < NN) g_rowptr[i + 1] = x;
    if (t == 1023) g_bsum[b] = ws[31];
    if (b == 0 && t == 0) g_rowptr[0] = 0;
}

__global__ void scan2_kernel(int nblk) {
    int t = threadIdx.x;
    int v = (t < nblk) ? g_bsum[t] : 0;
#pragma unroll
    for (int o = 1; o < 32; o <<= 1) {
        int y = __shfl_up_sync(0xffffffffu, v, o);
        if (t >= o) v += y;
    }
    if (t < nblk) g_bsum[t] = v;
}

__global__ void scan3_kernel() {
    int i = blockIdx.x * blockDim.x + threadIdx.x;
    if (i >= NN) return;
    int b = i >> 10;
    if (b > 0) g_rowptr[i + 1] += g_bsum[b - 1];
}

__global__ void scatter_kernel(const int* __restrict__ ei) {
    int e = blockIdx.x * blockDim.x + threadIdx.x;
    if (e < NE2) {
        int dst = (e < NE) ? ei[NE + e] : (e - NE);
        int pos = atomicAdd(&g_cursor[dst], 1);
        g_csr[g_rowptr[dst] + pos] = e;
    }
}

// ---------------- split x + weights once into hi/lo bf16 pool ----------------
__global__ void split_kernel(const float* __restrict__ x, const float* __restrict__ emb_w,
                             const float* __restrict__ lin_l, const float* __restrict__ lin_r,
                             const float* __restrict__ proj_w, const float* __restrict__ fw1,
                             const float* __restrict__ fw2) {
    int i = blockIdx.x * blockDim.x + threadIdx.x;
    if (i >= W_TOTAL) return;
    float v;
    if (i < OFF_EMB)       v = x[i - OFF_X];
    else if (i < OFF_LINL) v = emb_w[i - OFF_EMB];
    else if (i < OFF_LINR) v = lin_l[i - OFF_LINL];
    else if (i < OFF_PROJ) v = lin_r[i - OFF_LINR];
    else if (i < OFF_FW1)  v = proj_w[i - OFF_PROJ];
    else if (i < OFF_FW2)  v = fw1[i - OFF_FW1];
    else                   v = fw2[i - OFF_FW2];
    __nv_bfloat16 h = __float2bfloat16_rn(v);
    g_w_hi[i] = h;
    g_w_lo[i] = __float2bfloat16_rn(v - __bfloat162float(h));
}

// ---------------- split-bf16 tensor-core GEMM (3-pass compensated) ----------------
// inputs pre-split: A = Ahi+Alo, B = Bhi+Blo (f32-accurate to ~2^-18)
#define BM 128
#define BN 64
#define BK 16
#define SAH 24
#define SBH 72

__device__ __forceinline__ unsigned smaddr(const void* p) {
    return (unsigned)__cvta_generic_to_shared(p);
}

__device__ __forceinline__ void ldsm_x4(unsigned r[4], const void* p) {
    unsigned a = smaddr(p);
    asm volatile("ldmatrix.sync.aligned.m8n8.x4.shared.b16 {%0,%1,%2,%3},[%4];"
                 : "=r"(r[0]), "=r"(r[1]), "=r"(r[2]), "=r"(r[3]) : "r"(a));
}

__device__ __forceinline__ void ldsm_x4_t(unsigned r[4], const void* p) {
    unsigned a = smaddr(p);
    asm volatile("ldmatrix.sync.aligned.m8n8.x4.trans.shared.b16 {%0,%1,%2,%3},[%4];"
                 : "=r"(r[0]), "=r"(r[1]), "=r"(r[2]), "=r"(r[3]) : "r"(a));
}

__device__ __forceinline__ void mma16(float c[4], const unsigned a[4], unsigned b0, unsigned b1) {
    asm volatile(
        "mma.sync.aligned.m16n8k16.row.col.f32.bf16.bf16.f32 "
        "{%0,%1,%2,%3}, {%4,%5,%6,%7}, {%8,%9}, {%0,%1,%2,%3};"
        : "+f"(c[0]), "+f"(c[1]), "+f"(c[2]), "+f"(c[3])
        : "r"(a[0]), "r"(a[1]), "r"(a[2]), "r"(a[3]), "r"(b0), "r"(b1));
}

__global__ __launch_bounds__(256) void mma_gemm(
    const __nv_bfloat16* __restrict__ Ahi, const __nv_bfloat16* __restrict__ Alo,
    const __nv_bfloat16* __restrict__ Bhi, const __nv_bfloat16* __restrict__ Blo,
    const __nv_bfloat16* __restrict__ B2hi, const __nv_bfloat16* __restrict__ B2lo,
    const float* __restrict__ bias, const float* __restrict__ bias2,
    float* Cf, float* C2f, __nv_bfloat16* Chi, __nv_bfloat16* Clo,
    int n, int K, int N, int act) {
    if (blockIdx.z == 1) {
        Bhi = B2hi; Blo = B2lo; Cf = C2f; bias = bias2; Chi = 0; Clo = 0;
    }

    __shared__ __nv_bfloat16 As[2][2][BM * SAH];   // [buf][hi/lo]
    __shared__ __nv_bfloat16 Bs[2][2][BK * SBH];   // [buf][hi/lo]

    int tid = threadIdx.x;
    int warp = tid >> 5, lane = tid & 31;
    int g = lane >> 2, tg = lane & 3;
    int wm = warp >> 1, wn = warp & 1;
    int row0 = blockIdx.x * BM, col0 = blockIdx.y * BN;

    // loader indices: A: 2 threads/row (8 halves each); B: 128 threads per hi/lo plane
    int la_row = tid >> 1, la_ho = (tid & 1) * 8;
    int lb_r = (tid & 127) >> 3, lb_q = tid & 7;
    int lb_sel = tid >> 7;
    const __nv_bfloat16* Bsel = lb_sel ? Blo : Bhi;

    float c[2][4][4];
#pragma unroll
    for (int mi = 0; mi < 2; mi++)
#pragma unroll
        for (int ni = 0; ni < 4; ni++)
#pragma unroll
            for (int q = 0; q < 4; q++) c[mi][ni][q] = 0.f;

    int nk = K / BK;
    uint4 vah, val, vb;
    const uint4 z4 = make_uint4(0u, 0u, 0u, 0u);

    // prologue: tile 0
    {
        int gr = row0 + la_row;
        vah = val = z4;
        if (gr < n) {
            vah = *(const uint4*)&Ahi[(size_t)gr * K + la_ho];
            val = *(const uint4*)&Alo[(size_t)gr * K + la_ho];
        }
        vb = *(const uint4*)&Bsel[(size_t)lb_r * N + col0 + lb_q * 8];
        *(uint4*)&As[0][0][la_row * SAH + la_ho] = vah;
        *(uint4*)&As[0][1][la_row * SAH + la_ho] = val;
        *(uint4*)&Bs[0][lb_sel][lb_r * SBH + lb_q * 8] = vb;
    }
    __syncthreads();

    int a_row = wm * 32 + (lane & 15);
    int a_koff = (lane >> 4) * 8;
    int b_krow = lane & 15;
    int b_n0 = wn * 32 + (lane >> 4) * 8;

    for (int kb = 0; kb < nk; kb++) {
        int buf = kb & 1;
        bool more = (kb + 1 < nk);
        if (more) {
            int kk = (kb + 1) * BK;
            int gr = row0 + la_row;
            vah = val = z4;
            if (gr < n) {
                vah = *(const uint4*)&Ahi[(size_t)gr * K + kk + la_ho];
                val = *(const uint4*)&Alo[(size_t)gr * K + kk + la_ho];
            }
            vb = *(const uint4*)&Bsel[(size_t)(kk + lb_r) * N + col0 + lb_q * 8];
        }

        unsigned ah[2][4], al[2][4], bh[2][4], bl[2][4];
        ldsm_x4(ah[0], &As[buf][0][a_row * SAH + a_koff]);
        ldsm_x4(ah[1], &As[buf][0][(a_row + 16) * SAH + a_koff]);
        ldsm_x4(al[0], &As[buf][1][a_row * SAH + a_koff]);
        ldsm_x4(al[1], &As[buf][1][(a_row + 16) * SAH + a_koff]);
        ldsm_x4_t(bh[0], &Bs[buf][0][b_krow * SBH + b_n0]);
        ldsm_x4_t(bh[1], &Bs[buf][0][b_krow * SBH + b_n0 + 16]);
        ldsm_x4_t(bl[0], &Bs[buf][1][b_krow * SBH + b_n0]);
        ldsm_x4_t(bl[1], &Bs[buf][1][b_krow * SBH + b_n0 + 16]);

#pragma unroll
        for (int ni = 0; ni < 4; ni++) {
            int p = ni >> 1, w = ni & 1;
            unsigned bh0 = bh[p][w * 2], bh1 = bh[p][w * 2 + 1];
            unsigned bl0 = bl[p][w * 2], bl1 = bl[p][w * 2 + 1];
#pragma unroll
            for (int mi = 0; mi < 2; mi++) {
                mma16(c[mi][ni], ah[mi], bh0, bh1);   // hi*hi
                mma16(c[mi][ni], al[mi], bh0, bh1);   // lo*hi
                mma16(c[mi][ni], ah[mi], bl0, bl1);   // hi*lo
            }
        }

        if (more) {
            int nb = buf ^ 1;
            *(uint4*)&As[nb][0][la_row * SAH + la_ho] = vah;
            *(uint4*)&As[nb][1][la_row * SAH + la_ho] = val;
            *(uint4*)&Bs[nb][lb_sel][lb_r * SBH + lb_q * 8] = vb;
            __syncthreads();
        }
    }

    // epilogue: f32 and/or split bf16 outputs
#pragma unroll
    for (int mi = 0; mi < 2; mi++) {
#pragma unroll
        for (int ni = 0; ni < 4; ni++) {
            int r = row0 + wm * 32 + mi * 16 + g;
            int col = col0 + wn * 32 + ni * 8 + tg * 2;
            float b0v = bias ? __ldg(&bias[col]) : 0.f;
            float b1v = bias ? __ldg(&bias[col + 1]) : 0.f;
#pragma unroll
            for (int half = 0; half < 2; half++) {
                int rr = r + half * 8;
                if (rr >= n) continue;
                float v0 = c[mi][ni][half * 2 + 0] + b0v;
                float v1 = c[mi][ni][half * 2 + 1] + b1v;
                if (act) {
                    v0 = 0.5f * v0 * (1.0f + erff(v0 * 0.70710678118654752f));
                    v1 = 0.5f * v1 * (1.0f + erff(v1 * 0.70710678118654752f));
                }
                size_t idx = (size_t)rr * N + col;
                if (Cf) {
                    Cf[idx]     = v0;
                    Cf[idx + 1] = v1;
                }
                if (Chi) {
                    __nv_bfloat162 hh, ll;
                    hh.x = __float2bfloat16_rn(v0);
                    hh.y = __float2bfloat16_rn(v1);
                    ll.x = __float2bfloat16_rn(v0 - __bfloat162float(hh.x));
                    ll.y = __float2bfloat16_rn(v1 - __bfloat162float(hh.y));
                    *(__nv_bfloat162*)&Chi[idx] = hh;
                    *(__nv_bfloat162*)&Clo[idx] = ll;
                }
            }
        }
    }
}

// ---------------- fused GATv2: single-pass online softmax + aggregation ----------------
__global__ __launch_bounds__(256) void gat_fused_kernel(const int* __restrict__ ei,
                                                        const float* __restrict__ ea,
                                                        const float* __restrict__ We,
                                                        const float* __restrict__ att,
                                                        const float* __restrict__ bias,
                                                        int wsplit) {
    int gw = (blockIdx.x * blockDim.x + threadIdx.x) >> 5;
    int lane = threadIdx.x & 31;
    if (gw >= NN * HEADS) return;
    int n = gw >> 2, h = gw & 3;
    int beg = g_rowptr[n], end = g_rowptr[n + 1];

    float xr[4], w0[4], w1[4], at[4];
#pragma unroll
    for (int k = 0; k < 4; k++) {
        int cc = h * H + lane + 32 * k;
        xr[k] = g_xr[(size_t)n * HH + cc];
        w0[k] = __ldg(&We[cc]);
        w1[k] = __ldg(&We[HH + cc]);
        at[k] = __ldg(&att[cc]);
    }
    float la0 = g_la[2 * n], la1 = g_la[2 * n + 1];

    float m = -1e30f, denom = 0.f;
    float acc[4] = {0.f, 0.f, 0.f, 0.f};

    for (int j = beg; j < end; j++) {
        int e = g_csr[j];
        int src; float a0, a1;
        if (e < NE) {
            src = __ldg(&ei[e]);
            a0 = __ldg(&ea[2 * e]);
            a1 = __ldg(&ea[2 * e + 1]);
        } else {
            src = n; a0 = la0; a1 = la1;
        }
        const float* xs = g_xl + (size_t)src * HH + h * H + lane;
        float xl[4];
        float p = 0.f;
#pragma unroll
        for (int k = 0; k < 4; k++) {
            xl[k] = __ldg(xs + 32 * k);
            float v = xl[k] + xr[k] + a0 * w0[k] + a1 * w1[k];
            v = v > 0.f ? v : 0.2f * v;
            p += v * at[k];
        }
#pragma unroll
        for (int o = 16; o; o >>= 1) p += __shfl_xor_sync(0xffffffffu, p, o);
        if (p > m) {
            float sc = __expf(m - p);
            denom *= sc;
#pragma unroll
            for (int k = 0; k < 4; k++) acc[k] *= sc;
            m = p;
        }
        float w = __expf(p - m);
        denom += w;
#pragma unroll
        for (int k = 0; k < 4; k++) acc[k] += w * xl[k];
    }

    float inv = 1.0f / (denom + 1e-16f);
#pragma unroll
    for (int k = 0; k < 4; k++) {
        size_t idx = (size_t)n * HH + h * H + lane + 32 * k;
        float bv = bias ? __ldg(&bias[h * H + lane + 32 * k]) : 0.f;
        float v = acc[k] * inv + bv;
        g_agg[idx] = v;
        if (wsplit) {
            __nv_bfloat16 hh = __float2bfloat16_rn(v);
            g_aggs_hi[idx] = hh;
            g_aggs_lo[idx] = __float2bfloat16_rn(v - __bfloat162float(hh));
        }
    }
}

// layer-2: mean over heads + bias
__global__ void headmean_kernel(const float* __restrict__ bias2) {
    int idx = blockIdx.x * blockDim.x + threadIdx.x;
    if (idx >= NN * H) return;
    int n = idx >> 7, c = idx & 127;
    const float* a = g_agg + (size_t)n * HH;
    g_t[idx] = 0.25f * (a[c] + a[H + c] + a[2 * H + c] + a[3 * H + c]) + __ldg(&bias2[c]);
}

// warp-per-node LayerNorm: out = LN(a + res) * g + b; also emits split bf16
__global__ void ln_kernel(const float* __restrict__ a, const float* __restrict__ res,
                          const float* __restrict__ g, const float* __restrict__ b,
                          float* __restrict__ out) {
    int gw = (blockIdx.x * blockDim.x + threadIdx.x) >> 5;
    int lane = threadIdx.x & 31;
    if (gw >= NN) return;
    const float* pa = a + (size_t)gw * H;
    const float* pr = res + (size_t)gw * H;
    float v[4];
    float s = 0.f;
#pragma unroll
    for (int k = 0; k < 4; k++) {
        v[k] = pa[lane + 32 * k] + pr[lane + 32 * k];
        s += v[k];
    }
#pragma unroll
    for (int o = 16; o; o >>= 1) s += __shfl_xor_sync(0xffffffffu, s, o);
    float mu = s * (1.0f / 128.0f);
    float q = 0.f;
#pragma unroll
    for (int k = 0; k < 4; k++) {
        float d = v[k] - mu;
        q += d * d;
    }
#pragma unroll
    for (int o = 16; o; o >>= 1) q += __shfl_xor_sync(0xffffffffu, q, o);
    float r = rsqrtf(q * (1.0f / 128.0f) + 1e-5f);
    float* po = out + (size_t)gw * H;
#pragma unroll
    for (int k = 0; k < 4; k++) {
        int cc = lane + 32 * k;
        float o2 = (v[k] - mu) * r * __ldg(&g[cc]) + __ldg(&b[cc]);
        po[cc] = o2;
        size_t idx = (size_t)gw * H + cc;
        __nv_bfloat16 hh = __float2bfloat16_rn(o2);
        g_hs_hi[idx] = hh;
        g_hs_lo[idx] = __float2bfloat16_rn(o2 - __bfloat162float(hh));
    }
}

// ---------------- host ----------------
static void* sym(const void* s) {
    void* p = 0;
    cudaGetSymbolAddress(&p, s);
    return p;
}

extern "C" void kernel_launch(void* const* d_in, const int* in_sizes, int n_in,
                              void* d_out, int out_size) {
    const float* x        = (const float*)d_in[0];
    const int*   ei       = (const int*)d_in[1];
    const float* ea       = (const float*)d_in[2];
    const float* emb_w    = (const float*)d_in[3];
    const float* emb_b    = (const float*)d_in[4];
    const float* lin_l    = (const float*)d_in[5];
    const float* lin_r    = (const float*)d_in[6];
    const float* lin_edge = (const float*)d_in[7];
    const float* att      = (const float*)d_in[8];
    const float* cbias01  = (const float*)d_in[9];
    const float* cbias2   = (const float*)d_in[10];
    const float* proj_w   = (const float*)d_in[11];
    const float* proj_b   = (const float*)d_in[12];
    const float* n1_g     = (const float*)d_in[13];
    const float* n1_b     = (const float*)d_in[14];
    const float* n2_g     = (const float*)d_in[15];
    const float* n2_b     = (const float*)d_in[16];
    const float* ffn_w1   = (const float*)d_in[17];
    const float* ffn_b1   = (const float*)d_in[18];
    const float* ffn_w2   = (const float*)d_in[19];
    const float* ffn_b2   = (const float*)d_in[20];

    float* p_h   = (float*)sym(g_h);
    float* p_t   = (float*)sym(g_t);
    float* p_xl  = (float*)sym(g_xl);
    float* p_xr  = (float*)sym(g_xr);
    __nv_bfloat16* wh  = (__nv_bfloat16*)sym(g_w_hi);
    __nv_bfloat16* wl  = (__nv_bfloat16*)sym(g_w_lo);
    __nv_bfloat16* hsh = (__nv_bfloat16*)sym(g_hs_hi);
    __nv_bfloat16* hsl = (__nv_bfloat16*)sym(g_hs_lo);
    __nv_bfloat16* agh = (__nv_bfloat16*)sym(g_aggs_hi);
    __nv_bfloat16* agl = (__nv_bfloat16*)sym(g_aggs_lo);
    __nv_bfloat16* ffh = (__nv_bfloat16*)sym(g_ffns_hi);
    __nv_bfloat16* ffl = (__nv_bfloat16*)sym(g_ffns_lo);

    // graph setup + operand splitting
    int nblk = (NN + 1023) / 1024;
    zero_kernel<<<(NN + 255) / 256, 256>>>();
    deg_kernel<<<(NE + 255) / 256, 256>>>(ei, ea);
    split_kernel<<<(W_TOTAL + 255) / 256, 256>>>(x, emb_w, lin_l, lin_r, proj_w, ffn_w1, ffn_w2);
    loopattr_kernel<<<(NN + 255) / 256, 256>>>();
    scan1_kernel<<<nblk, 1024>>>();
    scan2_kernel<<<1, 32>>>(nblk);
    scan3_kernel<<<(NN + 255) / 256, 256>>>();
    scatter_kernel<<<(NE2 + 255) / 256, 256>>>(ei);

    int gx = (NN + BM - 1) / BM;

    // embedding: h = x @ emb_w + emb_b  (writes f32 + split)
    {
        dim3 grid(gx, H / BN, 1);
        mma_gemm<<<grid, 256>>>(wh + OFF_X, wl + OFF_X, wh + OFF_EMB, wl + OFF_EMB,
                                0, 0, emb_b, 0, p_h, 0, hsh, hsl, NN, 16, H, 0);
    }

    for (int i = 0; i < 3; i++) {
        const float* We = lin_edge + (size_t)i * 2 * HH;
        const float* At = att + (size_t)i * HEADS * H;
        size_t wo = (size_t)i * H * HH;

        // xl & xr in one launch (z=0 -> xl, z=1 -> xr)
        {
            dim3 grid(gx, HH / BN, 2);
            mma_gemm<<<grid, 256>>>(hsh, hsl,
                                    wh + OFF_LINL + wo, wl + OFF_LINL + wo,
                                    wh + OFF_LINR + wo, wl + OFF_LINR + wo,
                                    0, 0, p_xl, p_xr, 0, 0, NN, H, HH, 0);
        }

        {
            long thr = (long)NN * HEADS * 32;
            const float* bias = (i < 2) ? (cbias01 + (size_t)i * HH) : 0;
            gat_fused_kernel<<<(int)((thr + 255) / 256), 256>>>(ei, ea, We, At, bias, i < 2);
        }

        if (i < 2) {
            dim3 gp(gx, H / BN, 1);
            mma_gemm<<<gp, 256>>>(agh, agl,
                                  wh + OFF_PROJ + (size_t)i * HH * H,
                                  wl + OFF_PROJ + (size_t)i * HH * H,
                                  0, 0, proj_b + (size_t)i * H, 0,
                                  p_t, 0, 0, 0, NN, HH, H, 0);
        } else {
            headmean_kernel<<<(NN * H + 255) / 256, 256>>>(cbias2);
        }

        ln_kernel<<<(NN * 32 + 255) / 256, 256>>>(p_t, p_h, n1_g + (size_t)i * H,
                                                  n1_b + (size_t)i * H, p_h);

        // ffn1: gelu, split-only output
        {
            dim3 gf1(gx, 256 / BN, 1);
            mma_gemm<<<gf1, 256>>>(hsh, hsl,
                                   wh + OFF_FW1 + (size_t)i * H * 256,
                                   wl + OFF_FW1 + (size_t)i * H * 256,
                                   0, 0, ffn_b1 + (size_t)i * 256, 0,
                                   0, 0, ffh, ffl, NN, H, 256, 1);
        }
        // ffn2: f32 output
        {
            dim3 gf2(gx, H / BN, 1);
            mma_gemm<<<gf2, 256>>>(ffh, ffl,
                                   wh + OFF_FW2 + (size_t)i * 256 * H,
                                   wl + OFF_FW2 + (size_t)i * 256 * H,
                                   0, 0, ffn_b2 + (size_t)i * H, 0,
                                   p_t, 0, 0, 0, NN, 256, H, 0);
        }

        float* out_ptr = (i == 2) ? (float*)d_out : p_h;
        ln_kernel<<<(NN * 32 + 255) / 256, 256>>>(p_t, p_h, n2_g + (size_t)i * H,
                                                  n2_b + (size_t)i * H, out_ptr);
    }
}

// round 17
// speedup vs baseline: 1.1918x; 1.1918x over previous
#include <cuda_runtime.h>
#include <cuda_bf16.h>
#include <math.h>

#define NN 20000
#define NE 320000
#define NE2 (NE + NN)
#define H 128
#define HEADS 4
#define HH 512   // HEADS*H

// ---------------- static scratch (no allocation allowed) ----------------
__device__ float g_h[NN * H];
__device__ float g_t[NN * H];
__device__ float g_xl[NN * HH];
__device__ float g_xr[NN * HH];
__device__ float g_agg[NN * HH];
__device__ float g_ffn[NN * 256];
__device__ float g_la[NN * 2];
__device__ int   g_deg[NN];
__device__ int   g_rowptr[NN + 1];
__device__ int   g_cursor[NN];
__device__ int   g_csr[NE2];
__device__ int   g_bsum[32];

// ---------------- graph setup ----------------
__global__ void zero_kernel() {
    int i = blockIdx.x * blockDim.x + threadIdx.x;
    if (i < NN) {
        g_deg[i] = 0;
        g_cursor[i] = 0;
        g_la[2 * i] = 0.f;
        g_la[2 * i + 1] = 0.f;
    }
}

__global__ void deg_kernel(const int* __restrict__ ei, const float* __restrict__ ea) {
    int e = blockIdx.x * blockDim.x + threadIdx.x;
    if (e < NE) {
        int dst = ei[NE + e];
        atomicAdd(&g_deg[dst], 1);
        atomicAdd(&g_la[2 * dst],     ea[2 * e]);
        atomicAdd(&g_la[2 * dst + 1], ea[2 * e + 1]);
    }
}

__global__ void loopattr_kernel() {
    int n = blockIdx.x * blockDim.x + threadIdx.x;
    if (n < NN) {
        float d = fmaxf((float)g_deg[n], 1.0f);
        g_la[2 * n]     /= d;
        g_la[2 * n + 1] /= d;
    }
}

__global__ void scan1_kernel() {
    __shared__ int ws[32];
    int b = blockIdx.x, t = threadIdx.x;
    int i = b * 1024 + t;
    int lane = t & 31, w = t >> 5;
    int x = (i < NN) ? (g_deg[i] + 1) : 0;
#pragma unroll
    for (int o = 1; o < 32; o <<= 1) {
        int y = __shfl_up_sync(0xffffffffu, x, o);
        if (lane >= o) x += y;
    }
    if (lane == 31) ws[w] = x;
    __syncthreads();
    if (w == 0) {
        int s = ws[lane];
#pragma unroll
        for (int o = 1; o < 32; o <<= 1) {
            int y = __shfl_up_sync(0xffffffffu, s, o);
            if (lane >= o) s += y;
        }
        ws[lane] = s;
    }
    __syncthreads();
    int off = (w > 0) ? ws[w - 1] : 0;
    x += off;
    if (i < NN) g_rowptr[i + 1] = x;
    if (t == 1023) g_bsum[b] = ws[31];
    if (b == 0 && t == 0) g_rowptr[0] = 0;
}

__global__ void scan2_kernel(int nblk) {
    int t = threadIdx.x;
    int v = (t < nblk) ? g_bsum[t] : 0;
#pragma unroll
    for (int o = 1; o < 32; o <<= 1) {
        int y = __shfl_up_sync(0xffffffffu, v, o);
        if (t >= o) v += y;
    }
    if (t < nblk) g_bsum[t] = v;
}

__global__ void scan3_kernel() {
    int i = blockIdx.x * blockDim.x + threadIdx.x;
    if (i >= NN) return;
    int b = i >> 10;
    if (b > 0) g_rowptr[i + 1] += g_bsum[b - 1];
}

__global__ void scatter_kernel(const int* __restrict__ ei) {
    int e = blockIdx.x * blockDim.x + threadIdx.x;
    if (e < NE2) {
        int dst = (e < NE) ? ei[NE + e] : (e - NE);
        int pos = atomicAdd(&g_cursor[dst], 1);
        g_csr[g_rowptr[dst] + pos] = e;
    }
}

// ---------------- split-bf16 tensor-core GEMM (3-pass compensated) ----------------
// C[n,N] = act(A[n,K] @ B[K,N] + bias). K%16==0, N%64==0.
#define BM 128
#define BN 64
#define BK 16
#define SAH 24   // A smem row stride in halves
#define SBH 72   // B smem row stride in halves

__device__ __forceinline__ unsigned smaddr(const void* p) {
    return (unsigned)__cvta_generic_to_shared(p);
}

__device__ __forceinline__ void ldsm_x4(unsigned r[4], const void* p) {
    unsigned a = smaddr(p);
    asm volatile("ldmatrix.sync.aligned.m8n8.x4.shared.b16 {%0,%1,%2,%3},[%4];"
                 : "=r"(r[0]), "=r"(r[1]), "=r"(r[2]), "=r"(r[3]) : "r"(a));
}

__device__ __forceinline__ void ldsm_x4_t(unsigned r[4], const void* p) {
    unsigned a = smaddr(p);
    asm volatile("ldmatrix.sync.aligned.m8n8.x4.trans.shared.b16 {%0,%1,%2,%3},[%4];"
                 : "=r"(r[0]), "=r"(r[1]), "=r"(r[2]), "=r"(r[3]) : "r"(a));
}

__device__ __forceinline__ void mma16(float c[4], const unsigned a[4], unsigned b0, unsigned b1) {
    asm volatile(
        "mma.sync.aligned.m16n8k16.row.col.f32.bf16.bf16.f32 "
        "{%0,%1,%2,%3}, {%4,%5,%6,%7}, {%8,%9}, {%0,%1,%2,%3};"
        : "+f"(c[0]), "+f"(c[1]), "+f"(c[2]), "+f"(c[3])
        : "r"(a[0]), "r"(a[1]), "r"(a[2]), "r"(a[3]), "r"(b0), "r"(b1));
}

__device__ __forceinline__ void split4(float4 v, uint2& hi, uint2& lo) {
    float f[4] = {v.x, v.y, v.z, v.w};
    unsigned short hs[4], ls[4];
#pragma unroll
    for (int i = 0; i < 4; i++) {
        __nv_bfloat16 h = __float2bfloat16_rn(f[i]);
        float r = f[i] - __bfloat162float(h);
        __nv_bfloat16 l = __float2bfloat16_rn(r);
        hs[i] = __bfloat16_as_ushort(h);
        ls[i] = __bfloat16_as_ushort(l);
    }
    hi.x = (unsigned)hs[0] | ((unsigned)hs[1] << 16);
    hi.y = (unsigned)hs[2] | ((unsigned)hs[3] << 16);
    lo.x = (unsigned)ls[0] | ((unsigned)ls[1] << 16);
    lo.y = (unsigned)ls[2] | ((unsigned)ls[3] << 16);
}

__global__ __launch_bounds__(256) void mma_gemm(const float* __restrict__ A,
                                                const float* __restrict__ B,
                                                const float* __restrict__ B2,
                                                const float* __restrict__ bias,
                                                const float* __restrict__ bias2,
                                                float* Cf, float* C2f,
                                                int n, int K, int N, int act) {
    if (blockIdx.z == 1) { B = B2; Cf = C2f; bias = bias2; }

    __shared__ __nv_bfloat16 As[2][2][BM * SAH];   // [buf][hi/lo]
    __shared__ __nv_bfloat16 Bs[2][2][BK * SBH];   // [buf][hi/lo], layout [k][n]

    int tid = threadIdx.x;
    int warp = tid >> 5, lane = tid & 31;
    int g = lane >> 2, tg = lane & 3;
    int wm = warp >> 1, wn = warp & 1;
    int row0 = blockIdx.x * BM, col0 = blockIdx.y * BN;

    // loader indices
    int la_r = tid >> 2, la_q = tid & 3;              // A: two rows (tid, tid+256)
    int lb_r = tid >> 4, lb_q = tid & 15;             // B

    float c[2][4][4];
#pragma unroll
    for (int mi = 0; mi < 2; mi++)
#pragma unroll
        for (int ni = 0; ni < 4; ni++)
#pragma unroll
            for (int q = 0; q < 4; q++) c[mi][ni][q] = 0.f;

    int nk = K / BK;
    float4 ra0, ra1, rb;

    // prologue: load tile 0
    {
        int gr0 = row0 + la_r;
        int gr1 = row0 + la_r + 64;
        ra0 = (gr0 < n) ? *(const float4*)&A[(size_t)gr0 * K + la_q * 4]
                        : make_float4(0.f, 0.f, 0.f, 0.f);
        ra1 = (gr1 < n) ? *(const float4*)&A[(size_t)gr1 * K + la_q * 4]
                        : make_float4(0.f, 0.f, 0.f, 0.f);
        rb = *(const float4*)&B[(size_t)lb_r * N + col0 + lb_q * 4];
    }
    {
        uint2 h, l;
        split4(ra0, h, l);
        *(uint2*)&As[0][0][la_r * SAH + la_q * 4] = h;
        *(uint2*)&As[0][1][la_r * SAH + la_q * 4] = l;
        split4(ra1, h, l);
        *(uint2*)&As[0][0][(la_r + 64) * SAH + la_q * 4] = h;
        *(uint2*)&As[0][1][(la_r + 64) * SAH + la_q * 4] = l;
        split4(rb, h, l);
        *(uint2*)&Bs[0][0][lb_r * SBH + lb_q * 4] = h;
        *(uint2*)&Bs[0][1][lb_r * SBH + lb_q * 4] = l;
    }
    __syncthreads();

    // ldmatrix lane addressing
    int a_row = wm * 32 + (lane & 15);
    int a_koff = (lane >> 4) * 8;
    int b_krow = lane & 15;
    int b_n0 = wn * 32 + (lane >> 4) * 8;

    for (int kb = 0; kb < nk; kb++) {
        int buf = kb & 1;
        bool more = (kb + 1 < nk);
        if (more) {
            int kk = (kb + 1) * BK;
            int gr0 = row0 + la_r;
            int gr1 = row0 + la_r + 64;
            ra0 = (gr0 < n) ? *(const float4*)&A[(size_t)gr0 * K + kk + la_q * 4]
                            : make_float4(0.f, 0.f, 0.f, 0.f);
            ra1 = (gr1 < n) ? *(const float4*)&A[(size_t)gr1 * K + kk + la_q * 4]
                            : make_float4(0.f, 0.f, 0.f, 0.f);
            rb = *(const float4*)&B[(size_t)(kk + lb_r) * N + col0 + lb_q * 4];
        }

        unsigned ah[2][4], al[2][4], bh[2][4], bl[2][4];
        ldsm_x4(ah[0], &As[buf][0][a_row * SAH + a_koff]);
        ldsm_x4(ah[1], &As[buf][0][(a_row + 16) * SAH + a_koff]);
        ldsm_x4(al[0], &As[buf][1][a_row * SAH + a_koff]);
        ldsm_x4(al[1], &As[buf][1][(a_row + 16) * SAH + a_koff]);
        ldsm_x4_t(bh[0], &Bs[buf][0][b_krow * SBH + b_n0]);
        ldsm_x4_t(bh[1], &Bs[buf][0][b_krow * SBH + b_n0 + 16]);
        ldsm_x4_t(bl[0], &Bs[buf][1][b_krow * SBH + b_n0]);
        ldsm_x4_t(bl[1], &Bs[buf][1][b_krow * SBH + b_n0 + 16]);

#pragma unroll
        for (int ni = 0; ni < 4; ni++) {
            int p = ni >> 1, w = ni & 1;
            unsigned bh0 = bh[p][w * 2], bh1 = bh[p][w * 2 + 1];
            unsigned bl0 = bl[p][w * 2], bl1 = bl[p][w * 2 + 1];
#pragma unroll
            for (int mi = 0; mi < 2; mi++) {
                mma16(c[mi][ni], ah[mi], bh0, bh1);   // hi*hi
                mma16(c[mi][ni], al[mi], bh0, bh1);   // lo*hi
                mma16(c[mi][ni], ah[mi], bl0, bl1);   // hi*lo
            }
        }

        if (more) {
            int nb = buf ^ 1;
            uint2 h, l;
            split4(ra0, h, l);
            *(uint2*)&As[nb][0][la_r * SAH + la_q * 4] = h;
            *(uint2*)&As[nb][1][la_r * SAH + la_q * 4] = l;
            split4(ra1, h, l);
            *(uint2*)&As[nb][0][(la_r + 64) * SAH + la_q * 4] = h;
            *(uint2*)&As[nb][1][(la_r + 64) * SAH + la_q * 4] = l;
            split4(rb, h, l);
            *(uint2*)&Bs[nb][0][lb_r * SBH + lb_q * 4] = h;
            *(uint2*)&Bs[nb][1][lb_r * SBH + lb_q * 4] = l;
            __syncthreads();
        }
    }

    // epilogue
#pragma unroll
    for (int mi = 0; mi < 2; mi++) {
#pragma unroll
        for (int ni = 0; ni < 4; ni++) {
            int r = row0 + wm * 32 + mi * 16 + g;
            int col = col0 + wn * 32 + ni * 8 + tg * 2;
            float b0v = bias ? __ldg(&bias[col]) : 0.f;
            float b1v = bias ? __ldg(&bias[col + 1]) : 0.f;
            if (r < n) {
                float v0 = c[mi][ni][0] + b0v;
                float v1 = c[mi][ni][1] + b1v;
                if (act) {
                    v0 = 0.5f * v0 * (1.0f + erff(v0 * 0.70710678118654752f));
                    v1 = 0.5f * v1 * (1.0f + erff(v1 * 0.70710678118654752f));
                }
                Cf[(size_t)r * N + col]     = v0;
                Cf[(size_t)r * N + col + 1] = v1;
            }
            if (r + 8 < n) {
                float v2 = c[mi][ni][2] + b0v;
                float v3 = c[mi][ni][3] + b1v;
                if (act) {
                    v2 = 0.5f * v2 * (1.0f + erff(v2 * 0.70710678118654752f));
                    v3 = 0.5f * v3 * (1.0f + erff(v3 * 0.70710678118654752f));
                }
                Cf[(size_t)(r + 8) * N + col]     = v2;
                Cf[(size_t)(r + 8) * N + col + 1] = v3;
            }
        }
    }
}

// ---------------- fused GATv2: single-pass online softmax + aggregation ----------------
// one warp per (node, head); lane owns 4 consecutive channels (float4).
__global__ __launch_bounds__(256) void gat_fused_kernel(const int* __restrict__ ei,
                                                        const float* __restrict__ ea,
                                                        const float* __restrict__ We,
                                                        const float* __restrict__ att,
                                                        const float* __restrict__ bias) {
    int gw = (blockIdx.x * blockDim.x + threadIdx.x) >> 5;
    int lane = threadIdx.x & 31;
    if (gw >= NN * HEADS) return;
    int n = gw >> 2, h = gw & 3;
    int beg = g_rowptr[n], end = g_rowptr[n + 1];
    int cbase = h * H + lane * 4;

    float4 xr4 = *(const float4*)&g_xr[(size_t)n * HH + cbase];
    float4 w04 = __ldg((const float4*)&We[cbase]);
    float4 w14 = __ldg((const float4*)&We[HH + cbase]);
    float4 at4 = __ldg((const float4*)&att[cbase]);
    float la0 = g_la[2 * n], la1 = g_la[2 * n + 1];

    float m = -1e30f, denom = 0.f;
    float ax = 0.f, ay = 0.f, az = 0.f, aw = 0.f;

    for (int j = beg; j < end; j++) {
        int e = g_csr[j];
        int src; float a0, a1;
        if (e < NE) {
            src = __ldg(&ei[e]);
            a0 = __ldg(&ea[2 * e]);
            a1 = __ldg(&ea[2 * e + 1]);
        } else {
            src = n; a0 = la0; a1 = la1;
        }
        float4 xl4 = __ldg((const float4*)(g_xl + (size_t)src * HH + cbase));
        float v0 = xl4.x + xr4.x + a0 * w04.x + a1 * w14.x;
        float v1 = xl4.y + xr4.y + a0 * w04.y + a1 * w14.y;
        float v2 = xl4.z + xr4.z + a0 * w04.z + a1 * w14.z;
        float v3 = xl4.w + xr4.w + a0 * w04.w + a1 * w14.w;
        v0 = v0 > 0.f ? v0 : 0.2f * v0;
        v1 = v1 > 0.f ? v1 : 0.2f * v1;
        v2 = v2 > 0.f ? v2 : 0.2f * v2;
        v3 = v3 > 0.f ? v3 : 0.2f * v3;
        float p = v0 * at4.x + v1 * at4.y + v2 * at4.z + v3 * at4.w;
#pragma unroll
        for (int o = 16; o; o >>= 1) p += __shfl_xor_sync(0xffffffffu, p, o);
        // online softmax (p warp-uniform)
        if (p > m) {
            float sc = __expf(m - p);
            denom *= sc;
            ax *= sc; ay *= sc; az *= sc; aw *= sc;
            m = p;
        }
        float w = __expf(p - m);
        denom += w;
        ax += w * xl4.x; ay += w * xl4.y; az += w * xl4.z; aw += w * xl4.w;
    }

    float inv = 1.0f / (denom + 1e-16f);
    float4 bv = make_float4(0.f, 0.f, 0.f, 0.f);
    if (bias) bv = __ldg((const float4*)&bias[cbase]);
    float4 o4 = make_float4(ax * inv + bv.x, ay * inv + bv.y,
                            az * inv + bv.z, aw * inv + bv.w);
    *(float4*)&g_agg[(size_t)n * HH + cbase] = o4;
}

// layer-2: mean over heads + bias
__global__ void headmean_kernel(const float* __restrict__ bias2) {
    int idx = blockIdx.x * blockDim.x + threadIdx.x;
    if (idx >= NN * H) return;
    int n = idx >> 7, c = idx & 127;
    const float* a = g_agg + (size_t)n * HH;
    g_t[idx] = 0.25f * (a[c] + a[H + c] + a[2 * H + c] + a[3 * H + c]) + __ldg(&bias2[c]);
}

// warp-per-node LayerNorm: out = LN(a + res) * g + b
__global__ void ln_kernel(const float* __restrict__ a, const float* __restrict__ res,
                          const float* __restrict__ g, const float* __restrict__ b,
                          float* __restrict__ out) {
    int gw = (blockIdx.x * blockDim.x + threadIdx.x) >> 5;
    int lane = threadIdx.x & 31;
    if (gw >= NN) return;
    const float* pa = a + (size_t)gw * H;
    const float* pr = res + (size_t)gw * H;
    float v[4];
    float s = 0.f;
#pragma unroll
    for (int k = 0; k < 4; k++) {
        v[k] = pa[lane + 32 * k] + pr[lane + 32 * k];
        s += v[k];
    }
#pragma unroll
    for (int o = 16; o; o >>= 1) s += __shfl_xor_sync(0xffffffffu, s, o);
    float mu = s * (1.0f / 128.0f);
    float q = 0.f;
#pragma unroll
    for (int k = 0; k < 4; k++) {
        float d = v[k] - mu;
        q += d * d;
    }
#pragma unroll
    for (int o = 16; o; o >>= 1) q += __shfl_xor_sync(0xffffffffu, q, o);
    float r = rsqrtf(q * (1.0f / 128.0f) + 1e-5f);
    float* po = out + (size_t)gw * H;
#pragma unroll
    for (int k = 0; k < 4; k++) {
        int cc = lane + 32 * k;
        po[cc] = (v[k] - mu) * r * __ldg(&g[cc]) + __ldg(&b[cc]);
    }
}

// ---------------- host ----------------
static void* sym(const void* s) {
    void* p = 0;
    cudaGetSymbolAddress(&p, s);
    return p;
}

extern "C" void kernel_launch(void* const* d_in, const int* in_sizes, int n_in,
                              void* d_out, int out_size) {
    const float* x        = (const float*)d_in[0];
    const int*   ei       = (const int*)d_in[1];
    const float* ea       = (const float*)d_in[2];
    const float* emb_w    = (const float*)d_in[3];
    const float* emb_b    = (const float*)d_in[4];
    const float* lin_l    = (const float*)d_in[5];
    const float* lin_r    = (const float*)d_in[6];
    const float* lin_edge = (const float*)d_in[7];
    const float* att      = (const float*)d_in[8];
    const float* cbias01  = (const float*)d_in[9];
    const float* cbias2   = (const float*)d_in[10];
    const float* proj_w   = (const float*)d_in[11];
    const float* proj_b   = (const float*)d_in[12];
    const float* n1_g     = (const float*)d_in[13];
    const float* n1_b     = (const float*)d_in[14];
    const float* n2_g     = (const float*)d_in[15];
    const float* n2_b     = (const float*)d_in[16];
    const float* ffn_w1   = (const float*)d_in[17];
    const float* ffn_b1   = (const float*)d_in[18];
    const float* ffn_w2   = (const float*)d_in[19];
    const float* ffn_b2   = (const float*)d_in[20];

    float* p_h   = (float*)sym(g_h);
    float* p_t   = (float*)sym(g_t);
    float* p_xl  = (float*)sym(g_xl);
    float* p_xr  = (float*)sym(g_xr);
    float* p_agg = (float*)sym(g_agg);
    float* p_ffn = (float*)sym(g_ffn);

    // graph setup
    int nblk = (NN + 1023) / 1024;
    zero_kernel<<<(NN + 255) / 256, 256>>>();
    deg_kernel<<<(NE + 255) / 256, 256>>>(ei, ea);
    loopattr_kernel<<<(NN + 255) / 256, 256>>>();
    scan1_kernel<<<nblk, 1024>>>();
    scan2_kernel<<<1, 32>>>(nblk);
    scan3_kernel<<<(NN + 255) / 256, 256>>>();
    scatter_kernel<<<(NE2 + 255) / 256, 256>>>(ei);

    int gx = (NN + BM - 1) / BM;

    // embedding: h = x @ emb_w + emb_b  (K=16, N=128)
    {
        dim3 grid(gx, H / BN, 1);
        mma_gemm<<<grid, 256>>>(x, emb_w, 0, emb_b, 0, p_h, 0, NN, 16, H, 0);
    }

    for (int i = 0; i < 3; i++) {
        const float* Wl = lin_l + (size_t)i * H * HH;
        const float* Wr = lin_r + (size_t)i * H * HH;
        const float* We = lin_edge + (size_t)i * 2 * HH;
        const float* At = att + (size_t)i * HEADS * H;

        // xl & xr in one launch (z=0 -> xl, z=1 -> xr)
        {
            dim3 grid(gx, HH / BN, 2);
            mma_gemm<<<grid, 256>>>(p_h, Wl, Wr, 0, 0, p_xl, p_xr, NN, H, HH, 0);
        }

        {
            long thr = (long)NN * HEADS * 32;
            const float* bias = (i < 2) ? (cbias01 + (size_t)i * HH) : 0;
            gat_fused_kernel<<<(int)((thr + 255) / 256), 256>>>(ei, ea, We, At, bias);
        }

        if (i < 2) {
            dim3 gp(gx, H / BN, 1);
            mma_gemm<<<gp, 256>>>(p_agg, proj_w + (size_t)i * HH * H, 0,
                                  proj_b + (size_t)i * H, 0, p_t, 0, NN, HH, H, 0);
        } else {
            headmean_kernel<<<(NN * H + 255) / 256, 256>>>(cbias2);
        }

        ln_kernel<<<(NN * 32 + 255) / 256, 256>>>(p_t, p_h, n1_g + (size_t)i * H,
                                                  n1_b + (size_t)i * H, p_h);

        // ffn1: gelu (K=128, N=256)
        {
            dim3 gf1(gx, 256 / BN, 1);
            mma_gemm<<<gf1, 256>>>(p_h, ffn_w1 + (size_t)i * H * 256, 0,
                                   ffn_b1 + (size_t)i * 256, 0, p_ffn, 0, NN, H, 256, 1);
        }
        // ffn2 (K=256, N=128)
        {
            dim3 gf2(gx, H / BN, 1);
            mma_gemm<<<gf2, 256>>>(p_ffn, ffn_w2 + (size_t)i * 256 * H, 0,
                                   ffn_b2 + (size_t)i * H, 0, p_t, 0, NN, 256, H, 0);
        }

        float* out_ptr = (i == 2) ? (float*)d_out : p_h;
        ln_kernel<<<(NN * 32 + 255) / 256, 256>>>(p_t, p_h, n2_g + (size_t)i * H,
                                                  n2_b + (size_t)i * H, out_ptr);
    }
}